// round 11
// baseline (speedup 1.0000x reference)
#include <cuda_runtime.h>
#include <cuda_bf16.h>
#include <cstdint>

// ---------------------------------------------------------------------------
// DLRM small — split-bf16 GEMM chain.
// tcgen05 path (sm_103a): warp-specialized producer/consumer pipeline.
//   Warps 2-7 load (LDG -> fence.proxy.async -> STS -> arrive full);
//   thread 0 waits full, issues MMAs, commits empty[st]; a final commit to a
//   dedicated DONE mbarrier (single completion) gates the epilogue.
// Fallback path: mma.sync HMMA with cp.async (other targets).
// 3-pass split: acc += Ahi*Whi + Alo*Whi + Ahi*Wlo, fp32 accum.
// Weights pre-transposed to [N, Kpad] (K-major B operand).
// ---------------------------------------------------------------------------

#define BATCH 65536
#define VOCAB_MASK 0xFFFFFu

#if defined(__CUDA_ARCH_FEAT_SM103_ALL) || defined(__CUDA_ARCH_SPECIFIC__)
#define TC_PATH 1
#else
#define TC_PATH 0
#endif
#if !defined(__CUDA_ARCH__)
#undef TC_PATH
#define TC_PATH 0
#endif

// ---------------- scratch ----------------
__device__ __nv_bfloat16 g_p_hi[(size_t)BATCH * 1024];
__device__ __nv_bfloat16 g_p_lo[(size_t)BATCH * 1024];
__device__ __nv_bfloat16 g_q_hi[(size_t)BATCH * 1024];
__device__ __nv_bfloat16 g_q_lo[(size_t)BATCH * 1024];
__device__ __nv_bfloat16 g_h_hi[(size_t)BATCH * 128];
__device__ __nv_bfloat16 g_h_lo[(size_t)BATCH * 128];
__device__ __nv_bfloat16 g_wt_hi[2424832];
__device__ __nv_bfloat16 g_wt_lo[2424832];

// ---------------- common helpers ----------------
__device__ __forceinline__ void split2(float x, __nv_bfloat16& h, __nv_bfloat16& l) {
    h = __float2bfloat16(x);
    l = __float2bfloat16(x - __bfloat162float(h));
}
__device__ __forceinline__ void cp16(uint32_t dst, const void* src) {
    asm volatile("cp.async.cg.shared.global [%0], [%1], 16;\n" :: "r"(dst), "l"(src));
}
__device__ __forceinline__ void cp_commit() { asm volatile("cp.async.commit_group;\n"); }
__device__ __forceinline__ void cp_wait0()  { asm volatile("cp.async.wait_group 0;\n" ::: "memory"); }
__device__ __forceinline__ void cp_wait1()  { asm volatile("cp.async.wait_group 1;\n" ::: "memory"); }

__device__ __forceinline__ void ldsm4(uint32_t* r, uint32_t addr) {
    asm volatile("ldmatrix.sync.aligned.m8n8.x4.shared.b16 {%0,%1,%2,%3}, [%4];\n"
        : "=r"(r[0]), "=r"(r[1]), "=r"(r[2]), "=r"(r[3]) : "r"(addr));
}
__device__ __forceinline__ void mma16816(float* d, const uint32_t* a, const uint32_t* b) {
    asm volatile(
        "mma.sync.aligned.m16n8k16.row.col.f32.bf16.bf16.f32 "
        "{%0,%1,%2,%3}, {%4,%5,%6,%7}, {%8,%9}, {%0,%1,%2,%3};\n"
        : "+f"(d[0]), "+f"(d[1]), "+f"(d[2]), "+f"(d[3])
        : "r"(a[0]), "r"(a[1]), "r"(a[2]), "r"(a[3]), "r"(b[0]), "r"(b[1]));
}

// cp.async chunk loader (fallback path only)
template<int NT>
__device__ __forceinline__ void load_chunk_ca(
    uint32_t sb,
    const __nv_bfloat16* __restrict__ Ahi, const __nv_bfloat16* __restrict__ Alo,
    const __nv_bfloat16* __restrict__ Bhi, const __nv_bfloat16* __restrict__ Blo,
    int m0, int n0, int K, int k0, int tid)
{
    constexpr uint32_t BPL = NT * 128u;
    const int tot = 1024 + NT * 8;
    for (int q = tid; q < tot; q += 256) {
        if (q < 1024) {
            int row = q >> 3, seg = q & 7;
            uint32_t off = (uint32_t)(row * 128 + seg * 16);
            uint32_t sw = off ^ ((off >> 3) & 0x70u);
            size_t g = (size_t)(m0 + row) * K + k0 + seg * 8;
            cp16(sb + sw, Ahi + g);
            cp16(sb + 16384 + sw, Alo + g);
        } else {
            int r = q - 1024, row = r >> 3, seg = r & 7;
            uint32_t off = (uint32_t)(row * 128 + seg * 16);
            uint32_t sw = off ^ ((off >> 3) & 0x70u);
            size_t g = (size_t)(n0 + row) * K + k0 + seg * 8;
            cp16(sb + 32768 + sw, Bhi + g);
            cp16(sb + 32768 + BPL + sw, Blo + g);
        }
    }
}

// ---------------- tcgen05 helpers ----------------
#if TC_PATH
__device__ __forceinline__ uint64_t mkdesc(uint32_t addr) {
    const uint64_t base = 0x4000404000010000ULL;  // SW128, ver=1, SBO=64, LBO=1
    return base | ((uint64_t)(addr >> 4) & 0x3FFF);
}
__device__ __forceinline__ void mma_f16_ss(uint32_t d_tmem, uint64_t a_desc, uint64_t b_desc,
                                           uint32_t idesc, uint32_t enable) {
    asm volatile(
        "{\n\t"
        ".reg .pred p;\n\t"
        "setp.ne.u32 p, %5, 0;\n\t"
        "tcgen05.mma.cta_group::1.kind::f16 [%0], %1, %2, %3, {%4, %4, %4, %4}, p;\n\t"
        "}"
        :: "r"(d_tmem), "l"(a_desc), "l"(b_desc), "r"(idesc), "r"(0u), "r"(enable)
        : "memory");
}
#define TC_ALLOC(sa, n)   asm volatile("tcgen05.alloc.cta_group::1.sync.aligned.shared::cta.b32 [%0], %1;" :: "r"(sa), "r"(n) : "memory")
#define TC_DEALLOC(t, n)  asm volatile("tcgen05.dealloc.cta_group::1.sync.aligned.b32 %0, %1;" :: "r"(t), "r"(n))
#define TC_RELINQ()       asm volatile("tcgen05.relinquish_alloc_permit.cta_group::1.sync.aligned;")
#define TC_COMMIT(mb)     asm volatile("tcgen05.commit.cta_group::1.mbarrier::arrive::one.shared::cluster.b64 [%0];" :: "r"(mb) : "memory")
#define TC_FENCE_AFTER()  asm volatile("tcgen05.fence::after_thread_sync;" ::: "memory")
#define TC_WAIT_LD()      asm volatile("tcgen05.wait::ld.sync.aligned;" ::: "memory")
#define FENCE_ASYNC()     asm volatile("fence.proxy.async.shared::cta;" ::: "memory")
#define MB_INIT(mb, c)    asm volatile("mbarrier.init.shared.b64 [%0], %1;" :: "r"(mb), "r"(c) : "memory")
#define MB_ARRIVE(mb)     asm volatile("mbarrier.arrive.release.cta.shared::cta.b64 _, [%0];" :: "r"(mb) : "memory")

__device__ __forceinline__ void mb_wait(uint32_t mb, uint32_t parity) {
    asm volatile(
        "{\n\t"
        ".reg .pred P1;\n\t"
        "WAIT_LOOP_%=:\n\t"
        "mbarrier.try_wait.parity.acquire.cta.shared::cta.b64 P1, [%0], %1, 0x989680;\n\t"
        "@P1 bra.uni WAIT_DONE_%=;\n\t"
        "bra.uni WAIT_LOOP_%=;\n\t"
        "WAIT_DONE_%=:\n\t"
        "}"
        :: "r"(mb), "r"(parity) : "memory");
}
__device__ __forceinline__ void ldtm32(uint32_t* r, uint32_t ta) {
    asm volatile(
        "tcgen05.ld.sync.aligned.32x32b.x32.b32 "
        "{%0,%1,%2,%3,%4,%5,%6,%7,%8,%9,%10,%11,%12,%13,%14,%15,"
        "%16,%17,%18,%19,%20,%21,%22,%23,%24,%25,%26,%27,%28,%29,%30,%31}, [%32];"
        : "=r"(r[0]), "=r"(r[1]), "=r"(r[2]), "=r"(r[3]), "=r"(r[4]), "=r"(r[5]), "=r"(r[6]), "=r"(r[7]),
          "=r"(r[8]), "=r"(r[9]), "=r"(r[10]), "=r"(r[11]), "=r"(r[12]), "=r"(r[13]), "=r"(r[14]), "=r"(r[15]),
          "=r"(r[16]), "=r"(r[17]), "=r"(r[18]), "=r"(r[19]), "=r"(r[20]), "=r"(r[21]), "=r"(r[22]), "=r"(r[23]),
          "=r"(r[24]), "=r"(r[25]), "=r"(r[26]), "=r"(r[27]), "=r"(r[28]), "=r"(r[29]), "=r"(r[30]), "=r"(r[31])
        : "r"(ta));
}
// idesc: F32 acc, BF16 a/b, N=128/dispatch, M=128
constexpr uint32_t IDESC = (1u << 4) | (1u << 7) | (1u << 10) | (16u << 17) | (8u << 24);
#endif

// ---------------------------------------------------------------------------
// Unified GEMM: C[M,N] = relu(A@Wt^T + bias)
// A: [M,K] hi/lo planes. Wt: [N,K] hi/lo planes. K template constant.
// grid = (N/NT, M/128), 256 threads.
// ---------------------------------------------------------------------------
template<int NT, int K>
__global__ __launch_bounds__(256, 1) void gemm_tc(
    const __nv_bfloat16* __restrict__ Ahi, const __nv_bfloat16* __restrict__ Alo,
    const __nv_bfloat16* __restrict__ Bhi, const __nv_bfloat16* __restrict__ Blo,
    const float* __restrict__ bias,
    __nv_bfloat16* __restrict__ Chi, __nv_bfloat16* __restrict__ Clo,
    int ldc)
{
    extern __shared__ __align__(16) char smem_raw[];
    uint32_t sraw = (uint32_t)__cvta_generic_to_shared(smem_raw);
    const uint32_t s0 = (sraw + 1023u) & ~1023u;
    const uint32_t s_tile = s0 + 1024;
    constexpr uint32_t STG = 32768u + 2u * NT * 128u;
    constexpr int nk = K / 64;

    const int tid = threadIdx.x, w = tid >> 5, lane = tid & 31;
    const int m0 = blockIdx.y * 128;
    const int n0 = blockIdx.x * NT;

#if TC_PATH
    // ============ tcgen05 warp-specialized pipeline ============
    constexpr int nns = NT / 128;
    constexpr int TOT = 2048 + NT * 16;        // uint4 per stage
    constexpr int NLOAD = (TOT + 191) / 192;   // per producer thread
    const uint32_t FULL0 = s0 + 8,  FULL1 = s0 + 16;
    const uint32_t EMP0  = s0 + 24, EMP1  = s0 + 32;
    const uint32_t DONE  = s0 + 40;            // single-completion end barrier

    if (tid == 0) {
        MB_INIT(FULL0, 192); MB_INIT(FULL1, 192);
        MB_INIT(EMP0, 1);    MB_INIT(EMP1, 1);
        MB_INIT(DONE, 1);
    }
    if (w == 0) TC_ALLOC(s0, 512);
    __syncthreads();
    uint32_t tmem;
    asm volatile("ld.shared.b32 %0, [%1];" : "=r"(tmem) : "r"(s0));
    char* const smt = smem_raw + (s_tile - sraw);

    if (w >= 2) {
        // -------- producers (192 threads) --------
        const int tp = tid - 64;
        int eph[2] = {0, 0};
        for (int it = 0; it < nk; it++) {
            const int st = it & 1;
            if (it >= 2) {
                mb_wait((st ? EMP1 : EMP0), eph[st]);
                eph[st] ^= 1;
            }
            char* sb = smt + st * STG;
            const int k0 = it << 6;
#pragma unroll
            for (int i = 0; i < NLOAD; i++) {
                int q = i * 192 + tp;
                if (q < TOT) {
                    const __nv_bfloat16* src;
                    uint32_t pbase;
                    int a;
                    if (q < 1024)            { src = Ahi; pbase = 0;                 a = q; }
                    else if (q < 2048)       { src = Alo; pbase = 16384;             a = q - 1024; }
                    else if (q < 2048 + NT*8){ src = Bhi; pbase = 32768;             a = q - 2048; }
                    else                     { src = Blo; pbase = 32768 + NT * 128u; a = q - 2048 - NT * 8; }
                    int row = a >> 3, seg = a & 7;
                    uint32_t off = (uint32_t)(row * 128 + seg * 16);
                    uint32_t sw = off ^ ((off >> 3) & 0x70u);
                    const int grow = (q < 2048) ? (m0 + row) : (n0 + row);
                    uint4 v = *(const uint4*)(src + (size_t)grow * K + k0 + seg * 8);
                    *(uint4*)(sb + pbase + sw) = v;
                }
            }
            FENCE_ASYNC();   // order generic STS before async-proxy MMA reads
            MB_ARRIVE(st ? FULL1 : FULL0);
        }
    } else if (tid == 0) {
        // -------- MMA consumer --------
        int fph[2] = {0, 0};
        for (int it = 0; it < nk; it++) {
            const int st = it & 1;
            mb_wait((st ? FULL1 : FULL0), fph[st]);
            fph[st] ^= 1;
            const uint32_t sb = s_tile + st * STG;
            const uint64_t aD[2] = { mkdesc(sb), mkdesc(sb + 16384) };
            const uint64_t bD[2] = { mkdesc(sb + 32768), mkdesc(sb + 32768 + NT * 128u) };
#pragma unroll
            for (int p = 0; p < 3; p++) {
                uint64_t ad = aD[p == 1], bd = bD[p == 2];
#pragma unroll
                for (int ns = 0; ns < nns; ns++)
#pragma unroll
                    for (int k = 0; k < 4; k++)
                        mma_f16_ss(tmem + ns * 128, ad + k * 2, bd + ns * 1024 + k * 2,
                                   IDESC, (uint32_t)(it | p | k));
            }
            TC_COMMIT(st ? EMP1 : EMP0);
        }
        TC_COMMIT(DONE);   // signals once, after ALL prior MMAs complete
    }

    // -------- all threads: wait for the single DONE completion --------
    mb_wait(DONE, 0);
    TC_FENCE_AFTER();

    {
        float* ep = reinterpret_cast<float*>(smt + (size_t)w * 32 * 33 * 4);
        const int sp = w & 3;
        const int c_beg = (w >> 2) * (NT / 2);
        for (int c0 = c_beg; c0 < c_beg + NT / 2; c0 += 32) {
            uint32_t r[32];
            ldtm32(r, tmem + c0);
            TC_WAIT_LD();
#pragma unroll
            for (int j = 0; j < 32; j++) ep[lane * 33 + j] = __uint_as_float(r[j]);
            __syncwarp();
            const float bv = bias[n0 + c0 + lane];
#pragma unroll
            for (int rr = 0; rr < 32; rr++) {
                float x = fmaxf(ep[rr * 33 + lane] + bv, 0.f);
                __nv_bfloat16 h, l; split2(x, h, l);
                size_t o = (size_t)(m0 + sp * 32 + rr) * ldc + n0 + c0 + lane;
                Chi[o] = h; Clo[o] = l;
            }
            __syncwarp();
        }
    }
    __syncthreads();
    if (w == 0) { TC_RELINQ(); TC_DEALLOC(tmem, 512); }
#else
    // ============ HMMA fallback (cp.async) ============
    constexpr int NW = NT / 4;
    constexpr int N8 = NW / 8;
    const int wm = (w & 1) * 64;
    const int wn = (w >> 1) * NW;

    float acc[4][N8][4];
#pragma unroll
    for (int i = 0; i < 4; i++)
#pragma unroll
        for (int j = 0; j < N8; j++)
#pragma unroll
            for (int r = 0; r < 4; r++) acc[i][j][r] = 0.f;

    load_chunk_ca<NT>(s_tile, Ahi, Alo, Bhi, Blo, m0, n0, K, 0, tid);
    cp_commit();
    if (nk > 1) {
        load_chunk_ca<NT>(s_tile + STG, Ahi, Alo, Bhi, Blo, m0, n0, K, 64, tid);
        cp_commit();
    }

    for (int it = 0; it < nk; it++) {
        const int st = it & 1;
        if (it + 1 < nk) cp_wait1(); else cp_wait0();
        __syncthreads();
        const uint32_t sb = s_tile + st * STG;
#pragma unroll
        for (int kk = 0; kk < 4; kk++) {
            const uint32_t kb = kk * 32 + ((lane >> 4) * 16);
            uint32_t ah[4][4], al[4][4], bh[N8][2], bl[N8][2];
#pragma unroll
            for (int mi = 0; mi < 4; mi++) {
                uint32_t off = (uint32_t)((wm + mi * 16 + (lane & 15)) * 128) + kb;
                uint32_t sw = off ^ ((off >> 3) & 0x70u);
                ldsm4(ah[mi], sb + sw);
                ldsm4(al[mi], sb + 16384 + sw);
            }
#pragma unroll
            for (int nt = 0; nt < N8 / 2; nt++) {
                uint32_t off = (uint32_t)((wn + nt * 16 + (lane & 15)) * 128) + kb;
                uint32_t sw = off ^ ((off >> 3) & 0x70u);
                uint32_t t[4];
                ldsm4(t, sb + 32768 + sw);
                bh[nt * 2][0] = t[0]; bh[nt * 2][1] = t[2];
                bh[nt * 2 + 1][0] = t[1]; bh[nt * 2 + 1][1] = t[3];
                ldsm4(t, sb + 32768 + NT * 128u + sw);
                bl[nt * 2][0] = t[0]; bl[nt * 2][1] = t[2];
                bl[nt * 2 + 1][0] = t[1]; bl[nt * 2 + 1][1] = t[3];
            }
#pragma unroll
            for (int mi = 0; mi < 4; mi++)
#pragma unroll
                for (int j = 0; j < N8; j++) {
                    mma16816(acc[mi][j], ah[mi], bh[j]);
                    mma16816(acc[mi][j], al[mi], bh[j]);
                    mma16816(acc[mi][j], ah[mi], bl[j]);
                }
        }
        __syncthreads();
        if (it + 2 < nk) {
            load_chunk_ca<NT>(s_tile + st * STG, Ahi, Alo, Bhi, Blo, m0, n0, K, (it + 2) << 6, tid);
            cp_commit();
        }
    }

#pragma unroll
    for (int j = 0; j < N8; j++) {
        int c0 = n0 + wn + j * 8 + (lane & 3) * 2;
        float2 b2 = *reinterpret_cast<const float2*>(bias + c0);
#pragma unroll
        for (int mi = 0; mi < 4; mi++) {
            int r0 = m0 + wm + mi * 16 + (lane >> 2);
#pragma unroll
            for (int hrow = 0; hrow < 2; hrow++) {
                int r = r0 + hrow * 8;
                float x0 = fmaxf(acc[mi][j][hrow * 2 + 0] + b2.x, 0.f);
                float x1 = fmaxf(acc[mi][j][hrow * 2 + 1] + b2.y, 0.f);
                __nv_bfloat162 h2, l2;
                split2(x0, h2.x, l2.x);
                split2(x1, h2.y, l2.y);
                size_t o = (size_t)r * ldc + c0;
                *reinterpret_cast<__nv_bfloat162*>(Chi + o) = h2;
                *reinterpret_cast<__nv_bfloat162*>(Clo + o) = l2;
            }
        }
    }
#endif
}

// ---------------------------------------------------------------------------
// Fused conversions: dense -> p planes, 7 weights -> wt planes.
// ---------------------------------------------------------------------------
__global__ __launch_bounds__(256) void conv_all(
    const float* __restrict__ dense,
    const float* __restrict__ bw0, const float* __restrict__ bw1, const float* __restrict__ bw2,
    const float* __restrict__ tw0, const float* __restrict__ tw1, const float* __restrict__ tw2,
    const float* __restrict__ tw3,
    __nv_bfloat16* __restrict__ pHi, __nv_bfloat16* __restrict__ pLo,
    __nv_bfloat16* __restrict__ wHi, __nv_bfloat16* __restrict__ wLo)
{
    size_t idx = (size_t)blockIdx.x * 256 + threadIdx.x;
    const size_t ND = (size_t)BATCH * 64;
    if (idx < ND) {
        int row = (int)(idx >> 6), c = (int)(idx & 63);
        float x = (c < 13) ? dense[(size_t)row * 13 + c] : 0.f;
        split2(x, pHi[idx], pLo[idx]);
        return;
    }
    size_t wv = idx - ND;
    if (wv >= 2424832) return;
    const float* src; int K, N, ksh; size_t off;
    if      (wv < 32768)   { src = bw0; K = 13;   N = 512;  ksh = 6;  off = 0; }
    else if (wv < 163840)  { src = bw1; K = 512;  N = 256;  ksh = 9;  off = 32768; }
    else if (wv < 196608)  { src = bw2; K = 256;  N = 128;  ksh = 8;  off = 163840; }
    else if (wv < 720896)  { src = tw0; K = 506;  N = 1024; ksh = 9;  off = 196608; }
    else if (wv < 1769472) { src = tw1; K = 1024; N = 1024; ksh = 10; off = 720896; }
    else if (wv < 2293760) { src = tw2; K = 1024; N = 512;  ksh = 10; off = 1769472; }
    else                   { src = tw3; K = 512;  N = 256;  ksh = 9;  off = 2293760; }
    size_t l = wv - off;
    int n = (int)(l >> ksh), k = (int)(l & ((1u << ksh) - 1));
    float x = (k < K) ? src[(size_t)k * N + n] : 0.f;
    split2(x, wHi[wv], wLo[wv]);
}

// ---------------------------------------------------------------------------
__global__ __launch_bounds__(64) void interact2(
    const __nv_bfloat16* __restrict__ hhi, const __nv_bfloat16* __restrict__ hlo,
    const int* __restrict__ sidx, const float* __restrict__ emb,
    __nv_bfloat16* __restrict__ ohi, __nv_bfloat16* __restrict__ olo)
{
    __shared__ float comb[2][28][129];
    const int t = threadIdx.x;

    for (int idx = t; idx < 2 * 28 * 128; idx += 64) {
        int s = idx / (28 * 128);
        int rem = idx - s * 28 * 128;
        int j = rem >> 7, d = rem & 127;
        size_t row = (size_t)blockIdx.x * 2 + s;
        float v;
        if (j == 0)
            v = __bfloat162float(hhi[row * 128 + d]) + __bfloat162float(hlo[row * 128 + d]);
        else if (j <= 26) {
            unsigned e = ((unsigned)sidx[row * 26 + (j - 1)]) & VOCAB_MASK;
            v = emb[(size_t)e * 128 + d];
        } else v = 0.f;
        comb[s][j][d] = v;
    }
    __syncthreads();

    const int s = t >> 5, lane = t & 31;
    const size_t row = (size_t)blockIdx.x * 2 + s;
    __nv_bfloat16* oh = ohi + row * 512;
    __nv_bfloat16* ol = olo + row * 512;

    for (int d = lane; d < 128; d += 32) {
        oh[d] = hhi[row * 128 + d];
        ol[d] = hlo[row * 128 + d];
    }
    if (lane < 6) {
        oh[506 + lane] = __float2bfloat16(0.f);
        ol[506 + lane] = __float2bfloat16(0.f);
    }

    if (lane < 28) {
        int ty = 0, rem = lane;
        while (rem >= 7 - ty) { rem -= 7 - ty; ty++; }
        int tx = ty + rem;
        int i0 = ty * 4, j0 = tx * 4;

        float a4[4], b4[4], acc[4][4];
#pragma unroll
        for (int a = 0; a < 4; a++)
#pragma unroll
            for (int b = 0; b < 4; b++) acc[a][b] = 0.f;

#pragma unroll 4
        for (int d = 0; d < 128; d++) {
#pragma unroll
            for (int a = 0; a < 4; a++) a4[a] = comb[s][i0 + a][d];
#pragma unroll
            for (int b = 0; b < 4; b++) b4[b] = comb[s][j0 + b][d];
#pragma unroll
            for (int a = 0; a < 4; a++)
#pragma unroll
                for (int b = 0; b < 4; b++)
                    acc[a][b] = fmaf(a4[a], b4[b], acc[a][b]);
        }
#pragma unroll
        for (int a = 0; a < 4; a++) {
            int i = i0 + a;
#pragma unroll
            for (int b = 0; b < 4; b++) {
                int j = j0 + b;
                if (j >= i && i < 27 && j < 27) {
                    int p = 27 * i - (i * (i - 1)) / 2 + (j - i);
                    __nv_bfloat16 h, l;
                    split2(acc[a][b], h, l);
                    oh[128 + p] = h;
                    ol[128 + p] = l;
                }
            }
        }
    }
}

// ---------------------------------------------------------------------------
__global__ __launch_bounds__(256) void final_k(
    const __nv_bfloat16* __restrict__ Ahi, const __nv_bfloat16* __restrict__ Alo,
    const float* __restrict__ w, const float* __restrict__ bias, float* __restrict__ out)
{
    int warp = (blockIdx.x * blockDim.x + threadIdx.x) >> 5;
    int lane = threadIdx.x & 31;
    const __nv_bfloat16* ah = Ahi + (size_t)warp * 256;
    const __nv_bfloat16* al = Alo + (size_t)warp * 256;
    float s = 0.f;
#pragma unroll
    for (int i = 0; i < 8; i++) {
        int c = lane + i * 32;
        float a = __bfloat162float(ah[c]) + __bfloat162float(al[c]);
        s = fmaf(a, __ldg(&w[c]), s);
    }
#pragma unroll
    for (int o = 16; o; o >>= 1) s += __shfl_xor_sync(0xFFFFFFFFu, s, o);
    if (lane == 0) out[warp] = s + bias[0];
}

// ---------------------------------------------------------------------------
extern "C" void kernel_launch(void* const* d_in, const int* in_sizes, int n_in,
                              void* d_out, int out_size)
{
    const float* dense = (const float*)d_in[0];
    const int*   sidx  = (const int*)d_in[1];
    const float* emb   = (const float*)d_in[2];
    const float* bw0 = (const float*)d_in[3];  const float* bb0 = (const float*)d_in[4];
    const float* bw1 = (const float*)d_in[5];  const float* bb1 = (const float*)d_in[6];
    const float* bw2 = (const float*)d_in[7];  const float* bb2 = (const float*)d_in[8];
    const float* tw0 = (const float*)d_in[9];  const float* tb0 = (const float*)d_in[10];
    const float* tw1 = (const float*)d_in[11]; const float* tb1 = (const float*)d_in[12];
    const float* tw2 = (const float*)d_in[13]; const float* tb2 = (const float*)d_in[14];
    const float* tw3 = (const float*)d_in[15]; const float* tb3 = (const float*)d_in[16];
    const float* tw4 = (const float*)d_in[17]; const float* tb4 = (const float*)d_in[18];
    float* out = (float*)d_out;

    __nv_bfloat16 *pHi, *pLo, *qHi, *qLo, *hHi, *hLo, *wtHi, *wtLo;
    cudaGetSymbolAddress((void**)&pHi, g_p_hi);
    cudaGetSymbolAddress((void**)&pLo, g_p_lo);
    cudaGetSymbolAddress((void**)&qHi, g_q_hi);
    cudaGetSymbolAddress((void**)&qLo, g_q_lo);
    cudaGetSymbolAddress((void**)&hHi, g_h_hi);
    cudaGetSymbolAddress((void**)&hLo, g_h_lo);
    cudaGetSymbolAddress((void**)&wtHi, g_wt_hi);
    cudaGetSymbolAddress((void**)&wtLo, g_wt_lo);

    const int SM256 = 2048 + 2 * (32768 + 2 * 256 * 128);  // 198656
    const int SM128 = 2048 + 2 * (32768 + 2 * 128 * 128);  // 133120
    cudaFuncSetAttribute(gemm_tc<256, 64>,   cudaFuncAttributeMaxDynamicSharedMemorySize, SM256);
    cudaFuncSetAttribute(gemm_tc<256, 512>,  cudaFuncAttributeMaxDynamicSharedMemorySize, SM256);
    cudaFuncSetAttribute(gemm_tc<256, 1024>, cudaFuncAttributeMaxDynamicSharedMemorySize, SM256);
    cudaFuncSetAttribute(gemm_tc<128, 256>,  cudaFuncAttributeMaxDynamicSharedMemorySize, SM128);

    // transposed weight plane offsets ([N, Kpad])
    const size_t o0 = 0;                    // 512 x 64
    const size_t o1 = o0 + 512 * 64;        // 256 x 512
    const size_t o2 = o1 + 256 * 512;       // 128 x 256
    const size_t o3 = o2 + 128 * 256;       // 1024 x 512
    const size_t o4 = o3 + 1024 * 512;      // 1024 x 1024
    const size_t o5 = o4 + 1024 * 1024;     // 512 x 1024
    const size_t o6 = o5 + 512 * 1024;      // 256 x 512

    conv_all<<<25856, 256>>>(dense, bw0, bw1, bw2, tw0, tw1, tw2, tw3,
                             pHi, pLo, wtHi, wtLo);

    // bottom MLP
    gemm_tc<256, 64><<<dim3(2, 512), 256, SM256>>>(
        pHi, pLo, wtHi + o0, wtLo + o0, bb0, qHi, qLo, 512);
    gemm_tc<256, 512><<<dim3(1, 512), 256, SM256>>>(
        qHi, qLo, wtHi + o1, wtLo + o1, bb1, pHi, pLo, 256);
    gemm_tc<128, 256><<<dim3(1, 512), 256, SM128>>>(
        pHi, pLo, wtHi + o2, wtLo + o2, bb2, hHi, hLo, 128);

    // gather + interaction -> q planes (stride 512)
    interact2<<<BATCH / 2, 64>>>(hHi, hLo, sidx, emb, qHi, qLo);

    // top MLP
    gemm_tc<256, 512><<<dim3(4, 512), 256, SM256>>>(
        qHi, qLo, wtHi + o3, wtLo + o3, tb0, pHi, pLo, 1024);
    gemm_tc<256, 1024><<<dim3(4, 512), 256, SM256>>>(
        pHi, pLo, wtHi + o4, wtLo + o4, tb1, qHi, qLo, 1024);
    gemm_tc<256, 1024><<<dim3(2, 512), 256, SM256>>>(
        qHi, qLo, wtHi + o5, wtLo + o5, tb2, pHi, pLo, 512);
    gemm_tc<256, 512><<<dim3(1, 512), 256, SM256>>>(
        pHi, pLo, wtHi + o6, wtLo + o6, tb3, qHi, qLo, 256);

    // final 256 -> 1
    final_k<<<BATCH * 32 / 256, 256>>>(qHi, qLo, tw4, tb4, out);
}